// round 14
// baseline (speedup 1.0000x reference)
#include <cuda_runtime.h>
#include <cuda_fp16.h>
#include <cstdint>

#define CIN   256
#define CMID  512
#define COUT  256
#define IMGW  56
#define HW    3136
#define BATCH 32
#define KCONV 2304
#define PADW  58
#define PADPX 3496   // 58*58 = 3364 interior+borders, +132 zero tail

// ---------------- scratch (device globals — allocation-free rule) ----------------
__device__ __align__(16) __half g_xp  [(size_t)BATCH * PADPX * CIN];  // padded x [b][pidx][ci]
__device__ __align__(16) __half g_y16 [(size_t)BATCH * CMID * HW];    // y [b][cm][px]
__device__ __align__(16) __half g_wA16[CMID * KCONV];                 // [m][k], k = r*256+ci
__device__ __align__(16) __half g_wB16[COUT * CMID];                  // [cout][cm]

// ---------------- asm helpers ----------------
#define CP16(dst, src) \
    asm volatile("cp.async.cg.shared.global [%0], [%1], 16;\n" :: "r"(dst), "l"(src))
#define CP16Z(dst, src, sz) \
    asm volatile("cp.async.cg.shared.global [%0], [%1], 16, %2;\n" \
                 :: "r"(dst), "l"(src), "r"(sz))

#define MBAR_INIT(addr, cnt) \
    asm volatile("mbarrier.init.shared.b64 [%0], %1;" :: "r"(addr), "r"(cnt) : "memory")
#define MBAR_ARRIVE(addr) \
    asm volatile("mbarrier.arrive.shared.b64 _, [%0];" :: "r"(addr) : "memory")
#define CPASYNC_MBAR_ARRIVE(addr) \
    asm volatile("cp.async.mbarrier.arrive.noinc.shared.b64 [%0];" :: "r"(addr) : "memory")
#define MBAR_WAIT(addr, parity) do {                                              \
    uint32_t _done;                                                               \
    asm volatile("{.reg .pred p; "                                                \
        "mbarrier.try_wait.parity.acquire.cta.shared::cta.b64 p, [%1], %2;"       \
        "selp.b32 %0,1,0,p;}" : "=r"(_done) : "r"(addr), "r"(parity) : "memory"); \
    if (!_done) {                                                                 \
        asm volatile("{.reg .pred P1; WL_%=: "                                    \
            "mbarrier.try_wait.parity.acquire.cta.shared::cta.b64 P1, [%0], %1, 0x989680;" \
            "@P1 bra.uni WD_%=; bra.uni WL_%=; WD_%=:}"                           \
            :: "r"(addr), "r"(parity) : "memory");                                \
    } } while (0)

#define LDSM4(R0,R1,R2,R3,A) \
    asm volatile("ldmatrix.sync.aligned.m8n8.x4.shared.b16 {%0,%1,%2,%3}, [%4];" \
                 : "=r"(R0), "=r"(R1), "=r"(R2), "=r"(R3) : "r"(A))
#define LDSM4T(R0,R1,R2,R3,A) \
    asm volatile("ldmatrix.sync.aligned.m8n8.x4.trans.shared.b16 {%0,%1,%2,%3}, [%4];" \
                 : "=r"(R0), "=r"(R1), "=r"(R2), "=r"(R3) : "r"(A))

#define HMMA(C, A0,A1,A2,A3, B0,B1) \
    asm volatile("mma.sync.aligned.m16n8k16.row.col.f32.f16.f16.f32 " \
        "{%0,%1,%2,%3}, {%4,%5,%6,%7}, {%8,%9}, {%0,%1,%2,%3};\n" \
        : "+f"((C)[0]), "+f"((C)[1]), "+f"((C)[2]), "+f"((C)[3]) \
        : "r"(A0), "r"(A1), "r"(A2), "r"(A3), "r"(B0), "r"(B1))

// ---------------- prep kernels ----------------
__global__ void prep_xpad(const float* __restrict__ x) {
    __shared__ __half st[64][72];
    const int t   = threadIdx.x;
    const int px0 = blockIdx.x * 64;
    const int ci0 = blockIdx.y * 64;
    const int b   = blockIdx.z;
    #pragma unroll
    for (int i = 0; i < 16; ++i) {
        int id = i * 256 + t;
        int ci = id >> 6, px = id & 63;
        st[px][ci] = __float2half(
            x[((size_t)b * CIN + ci0 + ci) * HW + px0 + px]);
    }
    __syncthreads();
    #pragma unroll
    for (int i = 0; i < 8; ++i) {
        int id = i * 256 + t;
        int px = id >> 5, cc = id & 31;
        int opx = px0 + px;
        int oh = opx / IMGW, ow = opx % IMGW;
        int pidx = (oh + 1) * PADW + (ow + 1);
        __half2 v = *(__half2*)&st[px][cc * 2];
        *(__half2*)&g_xp[((size_t)b * PADPX + pidx) * CIN + ci0 + cc * 2] = v;
    }
}

__global__ void prep_wA16(const float* __restrict__ bw) {
    int idx = blockIdx.x * blockDim.x + threadIdx.x;
    if (idx >= CMID * KCONV) return;
    int k = idx % KCONV, m = idx / KCONV;
    int ci = k & 255, r = k >> 8;
    int kh = r / 3, kw = r % 3;
    g_wA16[idx] = __float2half(bw[((m * CIN + ci) * 3 + kh) * 3 + kw]);  // ternary exact
}
__global__ void prep_wB16(const float* __restrict__ fw) {
    int idx = blockIdx.x * blockDim.x + threadIdx.x;
    if (idx >= COUT * CMID) return;
    g_wB16[idx] = __float2half(fw[idx]);
}

// ---------------- fp16 HMMA GEMM, 512 threads, mbarrier pipeline ----------------
// Block 256(m) x 128(n), BK=64, 16 warps (4m x 4n), warp 64x32, 2 CTAs/SM
// => 32 warps/SM = 8/SMSP for latency hiding.
// 2 stages x 48KB (A 32KB + B 16KB). full[s] count 512 (cp.async-tracked),
// empty[s] count 16 (per-warp arrive).
#define STAGEB 49152
#define MBOFF  (2 * STAGEB)

template <bool CONV1>
__global__ __launch_bounds__(512, 2)
void conv_hmma(const float* __restrict__ bias, float* __restrict__ outp)
{
    constexpr int Ktot = CONV1 ? KCONV : CMID;
    constexpr int KT   = Ktot / 64;

    extern __shared__ char smem[];
    const uint32_t sb = (uint32_t)__cvta_generic_to_shared(smem);
    const int t    = threadIdx.x;
    const int lane = t & 31;
    const int warp = t >> 5;
    const int b    = blockIdx.z;
    const int mb   = blockIdx.y;
    const int n0   = blockIdx.x * 128;
    const int wm   = (warp & 3) * 64;
    const int wn   = (warp >> 2) * 32;

    if (t == 0) {
        #pragma unroll
        for (int s = 0; s < 2; ++s) {
            MBAR_INIT(sb + MBOFF + s * 8, 512);       // full[s]
            MBAR_INIT(sb + MBOFF + 16 + s * 8, 16);   // empty[s]
        }
    }
    __syncthreads();

    // ---- loop-invariant fragment address pieces ----
    const int r7  = lane & 7;
    const int c16 = lane >> 4;
    const int hi8 = ((lane >> 3) & 1) * 8;
    uint32_t cx[4];
    #pragma unroll
    for (int ks = 0; ks < 4; ++ks)
        cx[ks] = (uint32_t)((((ks * 2 + c16) ^ r7)) << 4);
    const uint32_t aRow  = (uint32_t)((wm + hi8 + r7) * 128);
    const uint32_t bRow1 = (uint32_t)((wn + hi8 + r7) * 128);   // conv1 B
    const uint32_t bRow2 = (uint32_t)((hi8 + r7) * 256);        // conv2 B (k-row base)
    uint32_t cx2[2];
    #pragma unroll
    for (int p = 0; p < 2; ++p)
        cx2[p] = (uint32_t)(((((wn >> 3) + p * 2 + c16)) ^ r7) << 4);

    // ---- cp.async invariants ----
    const int ar0 = t >> 3, ac8 = t & 7;      // A: 256 rows x 8 chunks, 4 per thread
    uint32_t adst[4];
    const __half* ap[4];
    {
        const __half* Asrc = (CONV1 ? g_wA16 : g_wB16) + (size_t)(mb * 256) * Ktot;
        #pragma unroll
        for (int i = 0; i < 4; ++i) {
            int row = ar0 + 64 * i;
            adst[i] = (uint32_t)(row * 128 + ((ac8 ^ (row & 7)) << 4));
            ap[i]   = Asrc + (size_t)row * Ktot + ac8 * 8;
        }
    }
    uint32_t bdst[2];
    const __half* bp[2];
    uint32_t bsz = 16;
    if (CONV1) {
        #pragma unroll
        for (int i = 0; i < 2; ++i) {
            int px  = i * 64 + (t >> 3);
            bdst[i] = (uint32_t)(px * 128 + ((ac8 ^ (px & 7)) << 4));
            int opx = n0 + px;
            int p00;
            if (opx < HW) {
                int oh = opx / IMGW, ow = opx % IMGW;
                p00 = oh * PADW + ow;          // tap(0,0) padded index
            } else {
                p00 = 3364;                    // zero page
            }
            bp[i] = g_xp + ((size_t)b * PADPX + p00) * CIN + ac8 * 8;
        }
    } else {
        const int c = t & 15;
        bsz = (n0 + c * 8) < HW ? 16u : 0u;
        #pragma unroll
        for (int i = 0; i < 2; ++i) {
            int row = i * 32 + (t >> 4);
            bdst[i] = (uint32_t)(row * 256 + ((c ^ (row & 7)) << 4));
            bp[i]   = g_y16 + ((size_t)b * CMID + row) * HW + n0 + c * 8;
        }
    }

    float acc[4][4][4];
    #pragma unroll
    for (int i = 0; i < 4; i++)
        #pragma unroll
        for (int j = 0; j < 4; j++)
            #pragma unroll
            for (int c = 0; c < 4; c++) acc[i][j][c] = 0.f;

    auto conv1_dk = [](int kt) -> int {
        int r  = kt >> 2;
        int kh = (r * 11) >> 5;        // r/3 for 0..8
        int kw = r - kh * 3;
        return (kh * PADW + kw) * CIN + (kt & 3) * 64;
    };

    auto issue_loads = [&](int kt, int s) {
        const uint32_t st = sb + s * STAGEB;
        #pragma unroll
        for (int i = 0; i < 4; ++i)
            CP16(st + adst[i], ap[i] + kt * 64);
        const uint32_t bst = st + 32768;
        if (CONV1) {
            const int dk = conv1_dk(kt);
            #pragma unroll
            for (int i = 0; i < 2; ++i)
                CP16(bst + bdst[i], bp[i] + dk);
        } else {
            const size_t dk = (size_t)(kt * 64) * HW;
            #pragma unroll
            for (int i = 0; i < 2; ++i)
                CP16Z(bst + bdst[i], bp[i] + dk, bsz);
        }
        CPASYNC_MBAR_ARRIVE(sb + MBOFF + s * 8);   // full[s] on completion
    };

    auto frag_step = [&](uint32_t sa, uint32_t bst, int ks) {
        uint32_t a[4][4], bf[4][2];
        #pragma unroll
        for (int mt = 0; mt < 4; ++mt)
            LDSM4(a[mt][0], a[mt][1], a[mt][2], a[mt][3],
                  sa + aRow + mt * 2048 + cx[ks]);
        #pragma unroll
        for (int p = 0; p < 2; ++p) {
            uint32_t r0, r1, r2, r3;
            if (CONV1) {
                LDSM4(r0, r1, r2, r3, bst + bRow1 + p * 2048 + cx[ks]);
                bf[p*2+0][0] = r0; bf[p*2+0][1] = r2;
                bf[p*2+1][0] = r1; bf[p*2+1][1] = r3;
            } else {
                LDSM4T(r0, r1, r2, r3, bst + bRow2 + ks * 4096 + cx2[p]);
                bf[p*2+0][0] = r0; bf[p*2+0][1] = r1;
                bf[p*2+1][0] = r2; bf[p*2+1][1] = r3;
            }
        }
        #pragma unroll
        for (int mt = 0; mt < 4; ++mt)
            #pragma unroll
            for (int nt = 0; nt < 4; ++nt)
                HMMA(acc[mt][nt], a[mt][0], a[mt][1], a[mt][2], a[mt][3],
                     bf[nt][0], bf[nt][1]);
    };

    // ---- 2-stage mbarrier pipeline ----
    issue_loads(0, 0);

    int fpar = 0, epar = 0;     // per-stage parity bitmasks
    for (int kt = 0; kt < KT; ++kt) {
        const int s = kt & 1;
        const uint32_t sa  = sb + s * STAGEB;
        const uint32_t bst = sa + 32768;
        MBAR_WAIT(sb + MBOFF + s * 8, (fpar >> s) & 1);
        frag_step(sa, bst, 0);
        if (kt + 1 < KT) {
            const int s2 = s ^ 1;
            if (kt + 1 >= 2) {   // stage s2 must be released by all warps (kt-1)
                MBAR_WAIT(sb + MBOFF + 16 + s2 * 8, (epar >> s2) & 1);
                epar ^= 1 << s2;
            }
            issue_loads(kt + 1, s2);
        }
        frag_step(sa, bst, 1);
        frag_step(sa, bst, 2);
        frag_step(sa, bst, 3);
        fpar ^= 1 << s;
        if (lane == 0) MBAR_ARRIVE(sb + MBOFF + 16 + s * 8);  // empty[s]
    }

    // ---- epilogue ----
    const int g  = lane >> 2;
    const int tt = (lane & 3) * 2;
    if (CONV1) {
        __half* dst = g_y16 + (size_t)b * CMID * HW;
        #pragma unroll
        for (int mt = 0; mt < 4; ++mt) {
            #pragma unroll
            for (int nt = 0; nt < 4; ++nt) {
                const int m   = mb * 256 + wm + mt * 16 + g;
                const int col = n0 + wn + nt * 8 + tt;
                if (col < HW) {
                    __half2 v0 = __floats2half2_rn(fmaxf(acc[mt][nt][0], 0.f),
                                                   fmaxf(acc[mt][nt][1], 0.f));
                    __half2 v1 = __floats2half2_rn(fmaxf(acc[mt][nt][2], 0.f),
                                                   fmaxf(acc[mt][nt][3], 0.f));
                    *(__half2*)&dst[(size_t)m * HW + col]       = v0;
                    *(__half2*)&dst[(size_t)(m + 8) * HW + col] = v1;
                }
            }
        }
    } else {
        float* dst = outp + (size_t)b * COUT * HW;
        #pragma unroll
        for (int mt = 0; mt < 4; ++mt) {
            #pragma unroll
            for (int nt = 0; nt < 4; ++nt) {
                const int m   = mb * 256 + wm + mt * 16 + g;
                const int col = n0 + wn + nt * 8 + tt;
                if (col < HW) {
                    const float b0 = bias[m], b1 = bias[m + 8];
                    float2 v0 = { acc[mt][nt][0] + b0, acc[mt][nt][1] + b0 };
                    float2 v1 = { acc[mt][nt][2] + b1, acc[mt][nt][3] + b1 };
                    *(float2*)&dst[(size_t)m * HW + col]       = v0;
                    *(float2*)&dst[(size_t)(m + 8) * HW + col] = v1;
                }
            }
        }
    }
}

extern "C" void kernel_launch(void* const* d_in, const int* in_sizes, int n_in,
                              void* d_out, int out_size) {
    (void)in_sizes; (void)n_in; (void)out_size;
    const float* x  = (const float*)d_in[0];
    const float* bw = (const float*)d_in[1];   // binary_w [512,256,3,3]
    const float* fw = (const float*)d_in[2];   // fc_w [256,512,1,1]
    const float* fb = (const float*)d_in[3];   // fc_b [256]
    float* out = (float*)d_out;

    const int smem_bytes = 2 * STAGEB + 64;   // 98368/CTA; 2 CTAs = 196KB <= 228KB
    cudaFuncSetAttribute(conv_hmma<true>,
                         cudaFuncAttributeMaxDynamicSharedMemorySize, smem_bytes);
    cudaFuncSetAttribute(conv_hmma<false>,
                         cudaFuncAttributeMaxDynamicSharedMemorySize, smem_bytes);

    prep_xpad <<<dim3(49, 4, 32), 256>>>(x);
    prep_wA16 <<<(CMID * KCONV + 255) / 256, 256>>>(bw);
    prep_wB16 <<<(COUT * CMID + 255) / 256, 256>>>(fw);

    // conv1 + relu -> g_y16 : M=512 (2 blocks of 256), N=3136 (25 tiles of 128)
    conv_hmma<true ><<<dim3(25, 2, 32), 512, smem_bytes>>>(nullptr, nullptr);
    // conv2 + bias -> out : M=256 (1 block)
    conv_hmma<false><<<dim3(25, 1, 32), 512, smem_bytes>>>(fb, out);
}

// round 16
// speedup vs baseline: 4.0571x; 4.0571x over previous
#include <cuda_runtime.h>
#include <cuda_fp16.h>
#include <cstdint>

#define CIN   256
#define CMID  512
#define COUT  256
#define IMGW  56
#define HW    3136
#define BATCH 32
#define KCONV 2304
#define PADW  58
#define PADPX 3496   // 58*58 = 3364 interior+borders, +132 zero tail

// ---------------- scratch (device globals — allocation-free rule) ----------------
__device__ __align__(16) __half g_xp  [(size_t)BATCH * PADPX * CIN];  // padded x [b][pidx][ci]
__device__ __align__(16) __half g_y16 [(size_t)BATCH * CMID * HW];    // y [b][cm][px]
__device__ __align__(16) __half g_wA16[CMID * KCONV];                 // [m][k], k = r*256+ci
__device__ __align__(16) __half g_wB16[COUT * CMID];                  // [cout][cm]

// ---------------- asm helpers ----------------
#define CP16(dst, src) \
    asm volatile("cp.async.cg.shared.global [%0], [%1], 16;\n" :: "r"(dst), "l"(src))
#define CP16Z(dst, src, sz) \
    asm volatile("cp.async.cg.shared.global [%0], [%1], 16, %2;\n" \
                 :: "r"(dst), "l"(src), "r"(sz))

#define MBAR_INIT(addr, cnt) \
    asm volatile("mbarrier.init.shared.b64 [%0], %1;" :: "r"(addr), "r"(cnt) : "memory")
#define CPASYNC_MBAR_ARRIVE(addr) \
    asm volatile("cp.async.mbarrier.arrive.noinc.shared.b64 [%0];" :: "r"(addr) : "memory")
#define MBAR_WAIT(addr, parity) do {                                              \
    uint32_t _done;                                                               \
    asm volatile("{.reg .pred p; "                                                \
        "mbarrier.try_wait.parity.acquire.cta.shared::cta.b64 p, [%1], %2;"       \
        "selp.b32 %0,1,0,p;}" : "=r"(_done) : "r"(addr), "r"(parity) : "memory"); \
    if (!_done) {                                                                 \
        asm volatile("{.reg .pred P1; WL_%=: "                                    \
            "mbarrier.try_wait.parity.acquire.cta.shared::cta.b64 P1, [%0], %1, 0x989680;" \
            "@P1 bra.uni WD_%=; bra.uni WL_%=; WD_%=:}"                           \
            :: "r"(addr), "r"(parity) : "memory");                                \
    } } while (0)

// Named barriers (ids 1..3): consumers arrive (non-blocking), refillers sync.
#define NBAR_ARRIVE(id) \
    asm volatile("bar.arrive %0, 512;" :: "r"(id) : "memory")
#define NBAR_SYNC(id) \
    asm volatile("bar.sync %0, 512;" :: "r"(id) : "memory")

#define LDSM4(R0,R1,R2,R3,A) \
    asm volatile("ldmatrix.sync.aligned.m8n8.x4.shared.b16 {%0,%1,%2,%3}, [%4];" \
                 : "=r"(R0), "=r"(R1), "=r"(R2), "=r"(R3) : "r"(A))
#define LDSM4T(R0,R1,R2,R3,A) \
    asm volatile("ldmatrix.sync.aligned.m8n8.x4.trans.shared.b16 {%0,%1,%2,%3}, [%4];" \
                 : "=r"(R0), "=r"(R1), "=r"(R2), "=r"(R3) : "r"(A))

#define HMMA(C, A0,A1,A2,A3, B0,B1) \
    asm volatile("mma.sync.aligned.m16n8k16.row.col.f32.f16.f16.f32 " \
        "{%0,%1,%2,%3}, {%4,%5,%6,%7}, {%8,%9}, {%0,%1,%2,%3};\n" \
        : "+f"((C)[0]), "+f"((C)[1]), "+f"((C)[2]), "+f"((C)[3]) \
        : "r"(A0), "r"(A1), "r"(A2), "r"(A3), "r"(B0), "r"(B1))

// ---------------- prep kernels ----------------
__global__ void prep_xpad(const float* __restrict__ x) {
    __shared__ __half st[64][72];
    const int t   = threadIdx.x;
    const int px0 = blockIdx.x * 64;
    const int ci0 = blockIdx.y * 64;
    const int b   = blockIdx.z;
    #pragma unroll
    for (int i = 0; i < 16; ++i) {
        int id = i * 256 + t;
        int ci = id >> 6, px = id & 63;
        st[px][ci] = __float2half(
            x[((size_t)b * CIN + ci0 + ci) * HW + px0 + px]);
    }
    __syncthreads();
    #pragma unroll
    for (int i = 0; i < 8; ++i) {
        int id = i * 256 + t;
        int px = id >> 5, cc = id & 31;
        int opx = px0 + px;
        int oh = opx / IMGW, ow = opx % IMGW;
        int pidx = (oh + 1) * PADW + (ow + 1);
        __half2 v = *(__half2*)&st[px][cc * 2];
        *(__half2*)&g_xp[((size_t)b * PADPX + pidx) * CIN + ci0 + cc * 2] = v;
    }
}

__global__ void prep_wA16(const float* __restrict__ bw) {
    int idx = blockIdx.x * blockDim.x + threadIdx.x;
    if (idx >= CMID * KCONV) return;
    int k = idx % KCONV, m = idx / KCONV;
    int ci = k & 255, r = k >> 8;
    int kh = r / 3, kw = r % 3;
    g_wA16[idx] = __float2half(bw[((m * CIN + ci) * 3 + kh) * 3 + kw]);  // ternary exact
}
__global__ void prep_wB16(const float* __restrict__ fw) {
    int idx = blockIdx.x * blockDim.x + threadIdx.x;
    if (idx >= COUT * CMID) return;
    g_wB16[idx] = __float2half(fw[idx]);
}

// ---------------- fp16 HMMA GEMM, mbarrier full + named-barrier empty ----------------
// Block 128x128, BK=64, 8 warps (2m x 4n), warp 64x32, 2 CTAs/SM, 3 stages x 32KB.
// fullB[s]: cp.async-tracked mbarrier (count 256). Stage-empty: named barrier
// id s+1, count 512 (256 consumer arrives + 256 refiller syncs).
// Load pointers advance incrementally (constant deltas) — no per-ktile recompute.
#define STAGEB 32768
#define MBOFF  (3 * STAGEB)    // fullB[3] @ +0

template <bool CONV1>
__global__ __launch_bounds__(256, 2)
void conv_hmma(const float* __restrict__ bias, float* __restrict__ outp)
{
    constexpr int Ktot = CONV1 ? KCONV : CMID;
    constexpr int KT   = Ktot / 64;

    extern __shared__ char smem[];
    const uint32_t sb = (uint32_t)__cvta_generic_to_shared(smem);
    const int t    = threadIdx.x;
    const int lane = t & 31;
    const int warp = t >> 5;
    const int b    = blockIdx.z;
    const int mb   = blockIdx.y;
    const int n0   = blockIdx.x * 128;
    const int wm   = (warp & 1) * 64;
    const int wn   = (warp >> 1) * 32;

    if (t == 0) {
        #pragma unroll
        for (int s = 0; s < 3; ++s)
            MBAR_INIT(sb + MBOFF + s * 8, 256);       // fullB[s]
    }
    __syncthreads();

    // ---- loop-invariant fragment address pieces ----
    const int r7  = lane & 7;
    const int c16 = lane >> 4;
    const int hi8 = ((lane >> 3) & 1) * 8;
    uint32_t cx[4];
    #pragma unroll
    for (int ks = 0; ks < 4; ++ks)
        cx[ks] = (uint32_t)((((ks * 2 + c16) ^ r7)) << 4);
    const uint32_t aRow  = (uint32_t)((wm + hi8 + r7) * 128);
    const uint32_t bRow1 = (uint32_t)((wn + hi8 + r7) * 128);   // conv1 B
    const uint32_t bRow2 = (uint32_t)((hi8 + r7) * 256);        // conv2 B (k-row base)
    uint32_t cx2[2];
    #pragma unroll
    for (int p = 0; p < 2; ++p)
        cx2[p] = (uint32_t)(((((wn >> 3) + p * 2 + c16)) ^ r7) << 4);

    // ---- cp.async invariants; pointers advance incrementally ----
    const int ar0 = t >> 3, ac8 = t & 7;
    uint32_t adst[4];
    const __half* aq[4];
    {
        const __half* Asrc = (CONV1 ? g_wA16 : g_wB16) + (size_t)(mb * 128) * Ktot;
        #pragma unroll
        for (int i = 0; i < 4; ++i) {
            int row = ar0 + 32 * i;
            adst[i] = (uint32_t)(row * 128 + ((ac8 ^ (row & 7)) << 4));
            aq[i]   = Asrc + (size_t)row * Ktot + ac8 * 8;   // at kt=0
        }
    }
    uint32_t bdst[4];
    const __half* bq[4];
    uint32_t bsz = 16;
    if (CONV1) {
        #pragma unroll
        for (int i = 0; i < 4; ++i) {
            int px  = i * 32 + (t >> 3);
            bdst[i] = (uint32_t)(px * 128 + ((ac8 ^ (px & 7)) << 4));
            int opx = n0 + px;
            int p00;
            if (opx < HW) {
                int oh = opx / IMGW, ow = opx % IMGW;
                p00 = oh * PADW + ow;          // tap(0,0) padded index
            } else {
                p00 = 3364;                    // zero page
            }
            bq[i] = g_xp + ((size_t)b * PADPX + p00) * CIN + ac8 * 8;  // at kt=0
        }
    } else {
        const int c = t & 15;
        bsz = (n0 + c * 8) < HW ? 16u : 0u;
        #pragma unroll
        for (int i = 0; i < 4; ++i) {
            int row = i * 16 + (t >> 4);
            bdst[i] = (uint32_t)(row * 256 + ((c ^ (row & 7)) << 4));
            bq[i]   = g_y16 + ((size_t)b * CMID + row) * HW + n0 + c * 8;  // at kt=0
        }
    }

    float acc[4][4][4];
    #pragma unroll
    for (int i = 0; i < 4; i++)
        #pragma unroll
        for (int j = 0; j < 4; j++)
            #pragma unroll
            for (int c = 0; c < 4; c++) acc[i][j][c] = 0.f;

    // advance pointers from state "issued kt" to "kt+1".
    // conv1: B delta +64 elems, except entering kt 12 or 24 (tap-row jump): +14144.
    // conv2: B delta +64*HW elems. A delta +64 always.
    auto advance = [&](int next_kt) {
        #pragma unroll
        for (int i = 0; i < 4; ++i) aq[i] += 64;
        if (CONV1) {
            int d = (next_kt == 12 || next_kt == 24) ? 14144 : 64;
            #pragma unroll
            for (int i = 0; i < 4; ++i) bq[i] += d;
        } else {
            #pragma unroll
            for (int i = 0; i < 4; ++i) bq[i] += (size_t)64 * HW;
        }
    };

    auto issue_loads = [&](int s) {
        const uint32_t st = sb + s * STAGEB;
        #pragma unroll
        for (int i = 0; i < 4; ++i)
            CP16(st + adst[i], aq[i]);
        const uint32_t bst = st + 16384;
        if (CONV1) {
            #pragma unroll
            for (int i = 0; i < 4; ++i)
                CP16(bst + bdst[i], bq[i]);
        } else {
            #pragma unroll
            for (int i = 0; i < 4; ++i)
                CP16Z(bst + bdst[i], bq[i], bsz);
        }
        CPASYNC_MBAR_ARRIVE(sb + MBOFF + s * 8);   // fullB[s] on completion
    };

    auto frag_step = [&](uint32_t sa, uint32_t bst, int ks) {
        uint32_t a[4][4], bf[4][2];
        #pragma unroll
        for (int mt = 0; mt < 4; ++mt)
            LDSM4(a[mt][0], a[mt][1], a[mt][2], a[mt][3],
                  sa + aRow + mt * 2048 + cx[ks]);
        #pragma unroll
        for (int p = 0; p < 2; ++p) {
            uint32_t r0, r1, r2, r3;
            if (CONV1) {
                LDSM4(r0, r1, r2, r3, bst + bRow1 + p * 2048 + cx[ks]);
                bf[p*2+0][0] = r0; bf[p*2+0][1] = r2;
                bf[p*2+1][0] = r1; bf[p*2+1][1] = r3;
            } else {
                LDSM4T(r0, r1, r2, r3, bst + bRow2 + ks * 4096 + cx2[p]);
                bf[p*2+0][0] = r0; bf[p*2+0][1] = r1;
                bf[p*2+1][0] = r2; bf[p*2+1][1] = r3;
            }
        }
        #pragma unroll
        for (int mt = 0; mt < 4; ++mt)
            #pragma unroll
            for (int nt = 0; nt < 4; ++nt)
                HMMA(acc[mt][nt], a[mt][0], a[mt][1], a[mt][2], a[mt][3],
                     bf[nt][0], bf[nt][1]);
    };

    // ---- prologue: fill stages 0,1 ----
    issue_loads(0);  advance(1);
    issue_loads(1);  advance(2);

    int s_cur = 0, s_nxt = 2;   // stage of kt, stage of kt+2
    int fpar = 0;               // fullB parity bitmask
    for (int kt = 0; kt < KT; ++kt) {
        const uint32_t sa  = sb + s_cur * STAGEB;
        const uint32_t bst = sa + 16384;
        MBAR_WAIT(sb + MBOFF + s_cur * 8, (fpar >> s_cur) & 1);   // data ready
        frag_step(sa, bst, 0);
        if (kt + 2 < KT) {
            if (kt + 2 >= 3)
                NBAR_SYNC(s_nxt + 1);      // all warps released stage s_nxt
            issue_loads(s_nxt);            // pointers are positioned at kt+2
            advance(kt + 3);
        }
        frag_step(sa, bst, 1);
        frag_step(sa, bst, 2);
        frag_step(sa, bst, 3);
        fpar ^= 1 << s_cur;
        NBAR_ARRIVE(s_cur + 1);            // release stage s_cur (non-blocking)
        s_cur = (s_cur == 2) ? 0 : s_cur + 1;
        s_nxt = (s_nxt == 2) ? 0 : s_nxt + 1;
    }

    // ---- epilogue ----
    const int g  = lane >> 2;
    const int tt = (lane & 3) * 2;
    if (CONV1) {
        __half* dst = g_y16 + (size_t)b * CMID * HW;
        #pragma unroll
        for (int mt = 0; mt < 4; ++mt) {
            #pragma unroll
            for (int nt = 0; nt < 4; ++nt) {
                const int m   = mb * 128 + wm + mt * 16 + g;
                const int col = n0 + wn + nt * 8 + tt;
                if (col < HW) {
                    __half2 v0 = __floats2half2_rn(fmaxf(acc[mt][nt][0], 0.f),
                                                   fmaxf(acc[mt][nt][1], 0.f));
                    __half2 v1 = __floats2half2_rn(fmaxf(acc[mt][nt][2], 0.f),
                                                   fmaxf(acc[mt][nt][3], 0.f));
                    *(__half2*)&dst[(size_t)m * HW + col]       = v0;
                    *(__half2*)&dst[(size_t)(m + 8) * HW + col] = v1;
                }
            }
        }
    } else {
        float* dst = outp + (size_t)b * COUT * HW;
        #pragma unroll
        for (int mt = 0; mt < 4; ++mt) {
            #pragma unroll
            for (int nt = 0; nt < 4; ++nt) {
                const int m   = mb * 128 + wm + mt * 16 + g;
                const int col = n0 + wn + nt * 8 + tt;
                if (col < HW) {
                    const float b0 = bias[m], b1 = bias[m + 8];
                    float2 v0 = { acc[mt][nt][0] + b0, acc[mt][nt][1] + b0 };
                    float2 v1 = { acc[mt][nt][2] + b1, acc[mt][nt][3] + b1 };
                    *(float2*)&dst[(size_t)m * HW + col]       = v0;
                    *(float2*)&dst[(size_t)(m + 8) * HW + col] = v1;
                }
            }
        }
    }
}

extern "C" void kernel_launch(void* const* d_in, const int* in_sizes, int n_in,
                              void* d_out, int out_size) {
    (void)in_sizes; (void)n_in; (void)out_size;
    const float* x  = (const float*)d_in[0];
    const float* bw = (const float*)d_in[1];   // binary_w [512,256,3,3]
    const float* fw = (const float*)d_in[2];   // fc_w [256,512,1,1]
    const float* fb = (const float*)d_in[3];   // fc_b [256]
    float* out = (float*)d_out;

    const int smem_bytes = 3 * STAGEB + 64;   // stages + fullB barriers
    cudaFuncSetAttribute(conv_hmma<true>,
                         cudaFuncAttributeMaxDynamicSharedMemorySize, smem_bytes);
    cudaFuncSetAttribute(conv_hmma<false>,
                         cudaFuncAttributeMaxDynamicSharedMemorySize, smem_bytes);

    prep_xpad <<<dim3(49, 4, 32), 256>>>(x);
    prep_wA16 <<<(CMID * KCONV + 255) / 256, 256>>>(bw);
    prep_wB16 <<<(COUT * CMID + 255) / 256, 256>>>(fw);

    // conv1 + relu -> g_y16 : M=512 (4 blocks of 128), N=3136 (25 tiles of 128)
    conv_hmma<true ><<<dim3(25, 4, 32), 256, smem_bytes>>>(nullptr, nullptr);
    // conv2 + bias -> out : M=256 (2 blocks)
    conv_hmma<false><<<dim3(25, 2, 32), 256, smem_bytes>>>(fb, out);
}

// round 17
// speedup vs baseline: 4.1849x; 1.0315x over previous
#include <cuda_runtime.h>
#include <cuda_fp16.h>
#include <cstdint>

#define CIN   256
#define CMID  512
#define COUT  256
#define IMGW  56
#define HW    3136
#define BATCH 32
#define KCONV 2304
#define PADW  58
#define PADPX 3496   // 58*58 = 3364 interior+borders, +132 zero tail

// ---------------- scratch (device globals — allocation-free rule) ----------------
__device__ __align__(16) __half g_xp  [(size_t)BATCH * PADPX * CIN];  // padded x [b][pidx][ci]
__device__ __align__(16) __half g_y16 [(size_t)BATCH * CMID * HW];    // y [b][cm][px]
__device__ __align__(16) __half g_wA16[CMID * KCONV];                 // [m][k], k = r*256+ci
__device__ __align__(16) __half g_wB16[COUT * CMID];                  // [cout][cm]

// ---------------- asm helpers ----------------
#define CP16(dst, src) \
    asm volatile("cp.async.cg.shared.global [%0], [%1], 16;\n" :: "r"(dst), "l"(src))
#define CP16Z(dst, src, sz) \
    asm volatile("cp.async.cg.shared.global [%0], [%1], 16, %2;\n" \
                 :: "r"(dst), "l"(src), "r"(sz))

#define MBAR_INIT(addr, cnt) \
    asm volatile("mbarrier.init.shared.b64 [%0], %1;" :: "r"(addr), "r"(cnt) : "memory")
#define MBAR_ARRIVE(addr) \
    asm volatile("mbarrier.arrive.shared.b64 _, [%0];" :: "r"(addr) : "memory")
#define CPASYNC_MBAR_ARRIVE(addr) \
    asm volatile("cp.async.mbarrier.arrive.noinc.shared.b64 [%0];" :: "r"(addr) : "memory")
#define MBAR_WAIT(addr, parity) do {                                              \
    uint32_t _done;                                                               \
    asm volatile("{.reg .pred p; "                                                \
        "mbarrier.try_wait.parity.acquire.cta.shared::cta.b64 p, [%1], %2;"       \
        "selp.b32 %0,1,0,p;}" : "=r"(_done) : "r"(addr), "r"(parity) : "memory"); \
    if (!_done) {                                                                 \
        asm volatile("{.reg .pred P1; WL_%=: "                                    \
            "mbarrier.try_wait.parity.acquire.cta.shared::cta.b64 P1, [%0], %1, 0x989680;" \
            "@P1 bra.uni WD_%=; bra.uni WL_%=; WD_%=:}"                           \
            :: "r"(addr), "r"(parity) : "memory");                                \
    } } while (0)

#define LDSM4(R0,R1,R2,R3,A) \
    asm volatile("ldmatrix.sync.aligned.m8n8.x4.shared.b16 {%0,%1,%2,%3}, [%4];" \
                 : "=r"(R0), "=r"(R1), "=r"(R2), "=r"(R3) : "r"(A))
#define LDSM4T(R0,R1,R2,R3,A) \
    asm volatile("ldmatrix.sync.aligned.m8n8.x4.trans.shared.b16 {%0,%1,%2,%3}, [%4];" \
                 : "=r"(R0), "=r"(R1), "=r"(R2), "=r"(R3) : "r"(A))

#define HMMA(C, A0,A1,A2,A3, B0,B1) \
    asm volatile("mma.sync.aligned.m16n8k16.row.col.f32.f16.f16.f32 " \
        "{%0,%1,%2,%3}, {%4,%5,%6,%7}, {%8,%9}, {%0,%1,%2,%3};\n" \
        : "+f"((C)[0]), "+f"((C)[1]), "+f"((C)[2]), "+f"((C)[3]) \
        : "r"(A0), "r"(A1), "r"(A2), "r"(A3), "r"(B0), "r"(B1))

// ---------------- prep kernels ----------------
__global__ void prep_xpad(const float* __restrict__ x) {
    __shared__ __half st[64][72];
    const int t   = threadIdx.x;
    const int px0 = blockIdx.x * 64;
    const int ci0 = blockIdx.y * 64;
    const int b   = blockIdx.z;
    #pragma unroll
    for (int i = 0; i < 16; ++i) {
        int id = i * 256 + t;
        int ci = id >> 6, px = id & 63;
        st[px][ci] = __float2half(
            x[((size_t)b * CIN + ci0 + ci) * HW + px0 + px]);
    }
    __syncthreads();
    #pragma unroll
    for (int i = 0; i < 8; ++i) {
        int id = i * 256 + t;
        int px = id >> 5, cc = id & 31;
        int opx = px0 + px;
        int oh = opx / IMGW, ow = opx % IMGW;
        int pidx = (oh + 1) * PADW + (ow + 1);
        __half2 v = *(__half2*)&st[px][cc * 2];
        *(__half2*)&g_xp[((size_t)b * PADPX + pidx) * CIN + ci0 + cc * 2] = v;
    }
}

// Fused weight prep: one launch covers conv1 (reorder) and conv2 (cast) weights.
__global__ void prep_w(const float* __restrict__ bw, const float* __restrict__ fw) {
    int idx = blockIdx.x * blockDim.x + threadIdx.x;
    if (idx < CMID * KCONV) {
        int k = idx % KCONV, m = idx / KCONV;
        int ci = k & 255, r = k >> 8;
        int kh = r / 3, kw = r % 3;
        g_wA16[idx] = __float2half(bw[((m * CIN + ci) * 3 + kh) * 3 + kw]);  // ternary exact
    } else {
        int j = idx - CMID * KCONV;
        if (j < COUT * CMID)
            g_wB16[j] = __float2half(fw[j]);
    }
}

// ---------------- fp16 HMMA GEMM, mbarrier stage pipeline (R13 champion) ----------------
// Block 128x128, BK=64, 8 warps (2m x 4n), warp 64x32, 2 CTAs/SM.
// 3 stages x 32KB. full[s]: cp.async-tracked (count 256); empty[s]: warp arrives
// (count 8). No per-ktile __syncthreads — warps progress independently.
#define STAGEB 32768
#define MBOFF  (3 * STAGEB)    // mbarriers: full[3] @ +0, empty[3] @ +24

template <bool CONV1>
__global__ __launch_bounds__(256, 2)
void conv_hmma(const float* __restrict__ bias, float* __restrict__ outp)
{
    constexpr int Ktot = CONV1 ? KCONV : CMID;
    constexpr int KT   = Ktot / 64;

    extern __shared__ char smem[];
    const uint32_t sb = (uint32_t)__cvta_generic_to_shared(smem);
    const int t    = threadIdx.x;
    const int lane = t & 31;
    const int warp = t >> 5;
    const int b    = blockIdx.z;
    const int mb   = blockIdx.y;
    const int n0   = blockIdx.x * 128;
    const int wm   = (warp & 1) * 64;
    const int wn   = (warp >> 1) * 32;

    // mbarrier init
    if (t == 0) {
        #pragma unroll
        for (int s = 0; s < 3; ++s) {
            MBAR_INIT(sb + MBOFF + s * 8, 256);       // full[s]
            MBAR_INIT(sb + MBOFF + 24 + s * 8, 8);    // empty[s]
        }
    }
    __syncthreads();

    // ---- loop-invariant fragment address pieces ----
    const int r7  = lane & 7;
    const int c16 = lane >> 4;
    const int hi8 = ((lane >> 3) & 1) * 8;
    uint32_t cx[4];
    #pragma unroll
    for (int ks = 0; ks < 4; ++ks)
        cx[ks] = (uint32_t)((((ks * 2 + c16) ^ r7)) << 4);
    const uint32_t aRow  = (uint32_t)((wm + hi8 + r7) * 128);
    const uint32_t bRow1 = (uint32_t)((wn + hi8 + r7) * 128);   // conv1 B
    const uint32_t bRow2 = (uint32_t)((hi8 + r7) * 256);        // conv2 B (k-row base)
    uint32_t cx2[2];
    #pragma unroll
    for (int p = 0; p < 2; ++p)
        cx2[p] = (uint32_t)(((((wn >> 3) + p * 2 + c16)) ^ r7) << 4);

    // ---- cp.async invariants ----
    const int ar0 = t >> 3, ac8 = t & 7;
    uint32_t adst[4];
    const __half* ap[4];
    {
        const __half* Asrc = (CONV1 ? g_wA16 : g_wB16) + (size_t)(mb * 128) * Ktot;
        #pragma unroll
        for (int i = 0; i < 4; ++i) {
            int row = ar0 + 32 * i;
            adst[i] = (uint32_t)(row * 128 + ((ac8 ^ (row & 7)) << 4));
            ap[i]   = Asrc + (size_t)row * Ktot + ac8 * 8;
        }
    }
    uint32_t bdst[4];
    const __half* bp[4];
    uint32_t bsz = 16;
    if (CONV1) {
        #pragma unroll
        for (int i = 0; i < 4; ++i) {
            int px  = i * 32 + (t >> 3);
            bdst[i] = (uint32_t)(px * 128 + ((ac8 ^ (px & 7)) << 4));
            int opx = n0 + px;
            int p00;
            if (opx < HW) {
                int oh = opx / IMGW, ow = opx % IMGW;
                p00 = oh * PADW + ow;          // tap(0,0) padded index
            } else {
                p00 = 3364;                    // zero page
            }
            bp[i] = g_xp + ((size_t)b * PADPX + p00) * CIN + ac8 * 8;
        }
    } else {
        const int c = t & 15;
        bsz = (n0 + c * 8) < HW ? 16u : 0u;
        #pragma unroll
        for (int i = 0; i < 4; ++i) {
            int row = i * 16 + (t >> 4);
            bdst[i] = (uint32_t)(row * 256 + ((c ^ (row & 7)) << 4));
            bp[i]   = g_y16 + ((size_t)b * CMID + row) * HW + n0 + c * 8;
        }
    }

    float acc[4][4][4];
    #pragma unroll
    for (int i = 0; i < 4; i++)
        #pragma unroll
        for (int j = 0; j < 4; j++)
            #pragma unroll
            for (int c = 0; c < 4; c++) acc[i][j][c] = 0.f;

    auto conv1_dk = [](int kt) -> int {
        int r  = kt >> 2;
        int kh = (r * 11) >> 5;        // r/3 for 0..8
        int kw = r - kh * 3;
        return (kh * PADW + kw) * CIN + (kt & 3) * 64;
    };

    auto issue_loads = [&](int kt, int s) {
        const uint32_t st = sb + s * STAGEB;
        #pragma unroll
        for (int i = 0; i < 4; ++i)
            CP16(st + adst[i], ap[i] + kt * 64);
        const uint32_t bst = st + 16384;
        if (CONV1) {
            const int dk = conv1_dk(kt);
            #pragma unroll
            for (int i = 0; i < 4; ++i)
                CP16(bst + bdst[i], bp[i] + dk);
        } else {
            const size_t dk = (size_t)(kt * 64) * HW;
            #pragma unroll
            for (int i = 0; i < 4; ++i)
                CP16Z(bst + bdst[i], bp[i] + dk, bsz);
        }
        CPASYNC_MBAR_ARRIVE(sb + MBOFF + s * 8);   // full[s] on completion
    };

    auto frag_step = [&](uint32_t sa, uint32_t bst, int ks) {
        uint32_t a[4][4], bf[4][2];
        #pragma unroll
        for (int mt = 0; mt < 4; ++mt)
            LDSM4(a[mt][0], a[mt][1], a[mt][2], a[mt][3],
                  sa + aRow + mt * 2048 + cx[ks]);
        #pragma unroll
        for (int p = 0; p < 2; ++p) {
            uint32_t r0, r1, r2, r3;
            if (CONV1) {
                LDSM4(r0, r1, r2, r3, bst + bRow1 + p * 2048 + cx[ks]);
                bf[p*2+0][0] = r0; bf[p*2+0][1] = r2;
                bf[p*2+1][0] = r1; bf[p*2+1][1] = r3;
            } else {
                LDSM4T(r0, r1, r2, r3, bst + bRow2 + ks * 4096 + cx2[p]);
                bf[p*2+0][0] = r0; bf[p*2+0][1] = r1;
                bf[p*2+1][0] = r2; bf[p*2+1][1] = r3;
            }
        }
        #pragma unroll
        for (int mt = 0; mt < 4; ++mt)
            #pragma unroll
            for (int nt = 0; nt < 4; ++nt)
                HMMA(acc[mt][nt], a[mt][0], a[mt][1], a[mt][2], a[mt][3],
                     bf[nt][0], bf[nt][1]);
    };

    // ---- prologue: fill stages 0,1 (no empty wait on first round) ----
    issue_loads(0, 0);
    issue_loads(1, 1);

    int s_cur = 0, s_nxt = 2;   // stage of kt, stage of kt+2
    int fpar = 0, epar = 0;     // per-stage parity bitmasks
    for (int kt = 0; kt < KT; ++kt) {
        const uint32_t sa  = sb + s_cur * STAGEB;
        const uint32_t bst = sa + 16384;
        // consume: wait stage data ready
        MBAR_WAIT(sb + MBOFF + s_cur * 8, (fpar >> s_cur) & 1);
        frag_step(sa, bst, 0);
        // produce kt+2 into s_nxt once every warp released it (computed kt-1)
        if (kt + 2 < KT) {
            if (kt + 2 >= 3) {
                MBAR_WAIT(sb + MBOFF + 24 + s_nxt * 8, (epar >> s_nxt) & 1);
                epar ^= 1 << s_nxt;
            }
            issue_loads(kt + 2, s_nxt);
        }
        frag_step(sa, bst, 1);
        frag_step(sa, bst, 2);
        frag_step(sa, bst, 3);
        fpar ^= 1 << s_cur;
        if (lane == 0) MBAR_ARRIVE(sb + MBOFF + 24 + s_cur * 8);  // empty[s_cur]
        s_cur = (s_cur == 2) ? 0 : s_cur + 1;
        s_nxt = (s_nxt == 2) ? 0 : s_nxt + 1;
    }

    // ---- epilogue (no smem use; no barrier needed) ----
    const int g  = lane >> 2;
    const int tt = (lane & 3) * 2;
    if (CONV1) {
        __half* dst = g_y16 + (size_t)b * CMID * HW;
        #pragma unroll
        for (int mt = 0; mt < 4; ++mt) {
            #pragma unroll
            for (int nt = 0; nt < 4; ++nt) {
                const int m   = mb * 128 + wm + mt * 16 + g;
                const int col = n0 + wn + nt * 8 + tt;
                if (col < HW) {
                    __half2 v0 = __floats2half2_rn(fmaxf(acc[mt][nt][0], 0.f),
                                                   fmaxf(acc[mt][nt][1], 0.f));
                    __half2 v1 = __floats2half2_rn(fmaxf(acc[mt][nt][2], 0.f),
                                                   fmaxf(acc[mt][nt][3], 0.f));
                    *(__half2*)&dst[(size_t)m * HW + col]       = v0;
                    *(__half2*)&dst[(size_t)(m + 8) * HW + col] = v1;
                }
            }
        }
    } else {
        float* dst = outp + (size_t)b * COUT * HW;
        #pragma unroll
        for (int mt = 0; mt < 4; ++mt) {
            #pragma unroll
            for (int nt = 0; nt < 4; ++nt) {
                const int m   = mb * 128 + wm + mt * 16 + g;
                const int col = n0 + wn + nt * 8 + tt;
                if (col < HW) {
                    const float b0 = bias[m], b1 = bias[m + 8];
                    float2 v0 = { acc[mt][nt][0] + b0, acc[mt][nt][1] + b0 };
                    float2 v1 = { acc[mt][nt][2] + b1, acc[mt][nt][3] + b1 };
                    *(float2*)&dst[(size_t)m * HW + col]       = v0;
                    *(float2*)&dst[(size_t)(m + 8) * HW + col] = v1;
                }
            }
        }
    }
}

extern "C" void kernel_launch(void* const* d_in, const int* in_sizes, int n_in,
                              void* d_out, int out_size) {
    (void)in_sizes; (void)n_in; (void)out_size;
    const float* x  = (const float*)d_in[0];
    const float* bw = (const float*)d_in[1];   // binary_w [512,256,3,3]
    const float* fw = (const float*)d_in[2];   // fc_w [256,512,1,1]
    const float* fb = (const float*)d_in[3];   // fc_b [256]
    float* out = (float*)d_out;

    const int smem_bytes = 3 * STAGEB + 64;   // stages + mbarriers
    cudaFuncSetAttribute(conv_hmma<true>,
                         cudaFuncAttributeMaxDynamicSharedMemorySize, smem_bytes);
    cudaFuncSetAttribute(conv_hmma<false>,
                         cudaFuncAttributeMaxDynamicSharedMemorySize, smem_bytes);

    prep_xpad <<<dim3(49, 4, 32), 256>>>(x);
    prep_w    <<<(CMID * KCONV + COUT * CMID + 255) / 256, 256>>>(bw, fw);

    // conv1 + relu -> g_y16 : M=512 (4 blocks of 128), N=3136 (25 tiles of 128)
    conv_hmma<true ><<<dim3(25, 4, 32), 256, smem_bytes>>>(nullptr, nullptr);
    // conv2 + bias -> out : M=256 (2 blocks)
    conv_hmma<false><<<dim3(25, 2, 32), 256, smem_bytes>>>(fb, out);
}